// round 8
// baseline (speedup 1.0000x reference)
#include <cuda_runtime.h>

typedef unsigned long long u64;

#define Tn 128
#define Dn 32
#define Hn 64
#define Gn 192   // 3*H

#define NWARP 16
#define TPB 512
#define NGRP 4            // element groups per block
#define EPW 8             // batch elements per group
#define EPB (NGRP * EPW)  // 32 elements per block

// Weight layout: s[(k>>2)*768 + g*4 + (k&3)] = W[g][k]  (quad-of-k packed per row)
#define OFF_W0X 0                         // [8][768]
#define OFF_W0H (OFF_W0X + 8  * 768)     // 6144
#define OFF_W1I (OFF_W0H + 16 * 768)     // 18432
#define OFF_W1H (OFF_W1I + 16 * 768)     // 30720
#define OFF_H1  (OFF_W1H + 16 * 768)     // 43008: [4 grp][8 e][64]
#define OFF_H2  (OFF_H1 + NGRP * EPW * Hn)   // 45056
#define OFF_X   (OFF_H2 + NGRP * EPW * Hn)   // 47104: [4 grp][8 e][32]
#define OFF_P   (OFF_X + NGRP * EPW * Dn)    // 48128: [4 grp][2 hw][8 e][32 lane][4]
#define SMEM_FLOATS (OFF_P + NGRP * 2 * EPW * 32 * 4)  // 56320 floats = 225280 B

__device__ __forceinline__ void ffma2(u64& d, u64 a, u64 b) {
    asm("fma.rn.f32x2 %0, %1, %2, %0;" : "+l"(d) : "l"(a), "l"(b));
}
__device__ __forceinline__ float hsum2(u64 v) {
    float lo, hi;
    asm("mov.b64 {%0, %1}, %2;" : "=f"(lo), "=f"(hi) : "l"(v));
    return lo + hi;
}
__device__ __forceinline__ float sigmoid_f(float x) {
    return __fdividef(1.0f, 1.0f + __expf(-x));
}
__device__ __forceinline__ float tanh_f(float x) {
    float e = __expf(-2.0f * x);
    return __fdividef(1.0f - e, 1.0f + e);
}

struct u64x2 { u64 a, b; };
__device__ __forceinline__ u64x2 lds128(const float* p) {
    u64x2 r;
    ulonglong2 v = *(const ulonglong2*)p;
    r.a = v.x; r.b = v.y;
    return r;
}

__global__ void __launch_bounds__(TPB, 1)
gru_fused_kernel(const float* __restrict__ x,
                 const float* __restrict__ W_ih0, const float* __restrict__ W_hh0,
                 const float* __restrict__ b_ih0, const float* __restrict__ b_hh0,
                 const float* __restrict__ W_ih1, const float* __restrict__ W_hh1,
                 const float* __restrict__ b_ih1, const float* __restrict__ b_hh1,
                 const float* __restrict__ fc_w, const float* __restrict__ fc_b,
                 float* __restrict__ out)
{
    extern __shared__ float sm[];
    const int tid = threadIdx.x;

    // ---- stage weights ----
    for (int idx = tid; idx < Gn * Dn; idx += TPB) {
        int g = idx / Dn, k = idx - g * Dn;
        sm[OFF_W0X + (k >> 2) * 768 + g * 4 + (k & 3)] = W_ih0[idx];
    }
    for (int idx = tid; idx < Gn * Hn; idx += TPB) {
        int g = idx / Hn, k = idx - g * Hn;
        int d = (k >> 2) * 768 + g * 4 + (k & 3);
        sm[OFF_W0H + d] = W_hh0[idx];
        sm[OFF_W1I + d] = W_ih1[idx];
        sm[OFF_W1H + d] = W_hh1[idx];
    }

    const int warp = tid >> 5;
    const int lane = tid & 31;
    const int wg = warp & 3;            // element group
    const int hw = (warp >> 2) & 1;     // row half
    const int kh = warp >> 3;           // k half
    const int barid = 1 + wg;
    const int eb = blockIdx.x * EPB + wg * EPW;

    const int row = lane + 32 * hw;

    float* s_h1 = sm + OFF_H1 + wg * (EPW * Hn);
    float* s_h2 = sm + OFF_H2 + wg * (EPW * Hn);
    float* s_x  = sm + OFF_X  + wg * (EPW * Dn);
    float* s_pp = sm + OFF_P  + (wg * 2 + hw) * (EPW * 128);  // partials, my (wg,hw) slot

    // zero h state (kh==0 warps cover all rows via hw)
    if (kh == 0) {
#pragma unroll
        for (int e = 0; e < EPW; ++e) {
            s_h1[e * Hn + row] = 0.0f;
            s_h2[e * Hn + row] = 0.0f;
        }
    }

    // prefetch + stage x(t=0): kh==0 warps, each handles e in [4hw, 4hw+4)
    float xr[4];
    if (kh == 0) {
#pragma unroll
        for (int j = 0; j < 4; ++j) {
            int e = 4 * hw + j;
            xr[j] = x[(eb + e) * (Tn * Dn) + lane];
            s_x[e * Dn + lane] = xr[j];
        }
        // prefetch t=1
#pragma unroll
        for (int j = 0; j < 4; ++j) {
            int e = 4 * hw + j;
            xr[j] = x[((eb + e) * Tn + 1) * Dn + lane];
        }
    }
    __syncthreads();

    // biases for this warp's rows
    const float Br0  = b_ih0[row]       + b_hh0[row];
    const float Bz0  = b_ih0[row + 64]  + b_hh0[row + 64];
    const float Bxn0 = b_ih0[row + 128];
    const float Bhn0 = b_hh0[row + 128];
    const float Br1  = b_ih1[row]       + b_hh1[row];
    const float Bz1  = b_ih1[row + 64]  + b_hh1[row + 64];
    const float Bxn1 = b_ih1[row + 128];
    const float Bhn1 = b_hh1[row + 128];

    const int oR = row * 4;
    const int oZ = (row + 64) * 4;
    const int oN = (row + 128) * 4;

    u64 ar[EPW], az[EPW], axn[EPW], ahn[EPW];

    for (int t = 0; t < Tn; ++t) {
        // ================= layer 0: gemm over my k-half =================
#pragma unroll
        for (int e = 0; e < EPW; ++e) { ar[e] = 0; az[e] = 0; axn[e] = 0; ahn[e] = 0; }

        // x-side quads: kh*4 .. kh*4+3 (of 8)
#pragma unroll 2
        for (int qq = 0; qq < 4; ++qq) {
            int q = kh * 4 + qq;
            const float* wq = sm + OFF_W0X + q * 768;
            u64x2 wr = lds128(wq + oR);
            u64x2 wz = lds128(wq + oZ);
            u64x2 wn = lds128(wq + oN);
#pragma unroll
            for (int e = 0; e < EPW; ++e) {
                u64x2 xv = lds128(s_x + e * Dn + q * 4);
                ffma2(ar[e],  wr.a, xv.a); ffma2(ar[e],  wr.b, xv.b);
                ffma2(az[e],  wz.a, xv.a); ffma2(az[e],  wz.b, xv.b);
                ffma2(axn[e], wn.a, xv.a); ffma2(axn[e], wn.b, xv.b);
            }
        }
        // h-side quads: kh*8 .. kh*8+7 (of 16)
#pragma unroll 2
        for (int qq = 0; qq < 8; ++qq) {
            int q = kh * 8 + qq;
            const float* wq = sm + OFF_W0H + q * 768;
            u64x2 wr = lds128(wq + oR);
            u64x2 wz = lds128(wq + oZ);
            u64x2 wn = lds128(wq + oN);
#pragma unroll
            for (int e = 0; e < EPW; ++e) {
                u64x2 hv = lds128(s_h1 + e * Hn + q * 4);
                ffma2(ar[e],  wr.a, hv.a); ffma2(ar[e],  wr.b, hv.b);
                ffma2(az[e],  wz.a, hv.a); ffma2(az[e],  wz.b, hv.b);
                ffma2(ahn[e], wn.a, hv.a); ffma2(ahn[e], wn.b, hv.b);
            }
        }

        // phase-0 producer: kh==1 stores scalar partials
        if (kh == 1) {
#pragma unroll
            for (int e = 0; e < EPW; ++e) {
                float4 p;
                p.x = hsum2(ar[e]); p.y = hsum2(az[e]);
                p.z = hsum2(axn[e]); p.w = hsum2(ahn[e]);
                *(float4*)(s_pp + e * 128 + lane * 4) = p;
            }
        }
        asm volatile("bar.sync %0, %1;" :: "r"(barid), "r"(128) : "memory");  // #1

        // phase-0 consumer: kh==0 reduces + epilogue -> h1
        if (kh == 0) {
#pragma unroll
            for (int e = 0; e < EPW; ++e) {
                float4 p = *(const float4*)(s_pp + e * 128 + lane * 4);
                float r = sigmoid_f(hsum2(ar[e]) + p.x + Br0);
                float z = sigmoid_f(hsum2(az[e]) + p.y + Bz0);
                float n = tanh_f(fmaf(r, hsum2(ahn[e]) + p.w + Bhn0,
                                         hsum2(axn[e]) + p.z + Bxn0));
                float hp = s_h1[e * Hn + row];
                s_h1[e * Hn + row] = fmaf(z, hp - n, n);
            }
        }
        asm volatile("bar.sync %0, %1;" :: "r"(barid), "r"(128) : "memory");  // #2

        // ================= layer 1: gemm over my k-half =================
#pragma unroll
        for (int e = 0; e < EPW; ++e) { ar[e] = 0; az[e] = 0; axn[e] = 0; ahn[e] = 0; }

#pragma unroll 2
        for (int qq = 0; qq < 8; ++qq) {
            int q = kh * 8 + qq;
            {   // input side (new h1)
                const float* wqi = sm + OFF_W1I + q * 768;
                u64x2 ir = lds128(wqi + oR);
                u64x2 iz = lds128(wqi + oZ);
                u64x2 in = lds128(wqi + oN);
#pragma unroll
                for (int e = 0; e < EPW; ++e) {
                    u64x2 av = lds128(s_h1 + e * Hn + q * 4);
                    ffma2(ar[e],  ir.a, av.a); ffma2(ar[e],  ir.b, av.b);
                    ffma2(az[e],  iz.a, av.a); ffma2(az[e],  iz.b, av.b);
                    ffma2(axn[e], in.a, av.a); ffma2(axn[e], in.b, av.b);
                }
            }
            {   // hidden side (prev h2)
                const float* wqh = sm + OFF_W1H + q * 768;
                u64x2 hr = lds128(wqh + oR);
                u64x2 hz = lds128(wqh + oZ);
                u64x2 hn = lds128(wqh + oN);
#pragma unroll
                for (int e = 0; e < EPW; ++e) {
                    u64x2 bv = lds128(s_h2 + e * Hn + q * 4);
                    ffma2(ar[e],  hr.a, bv.a); ffma2(ar[e],  hr.b, bv.b);
                    ffma2(az[e],  hz.a, bv.a); ffma2(az[e],  hz.b, bv.b);
                    ffma2(ahn[e], hn.a, bv.a); ffma2(ahn[e], hn.b, bv.b);
                }
            }
        }

        // phase-1 producer: kh==0 stores partials, stages x(t+1), prefetches x(t+2)
        if (kh == 0) {
#pragma unroll
            for (int e = 0; e < EPW; ++e) {
                float4 p;
                p.x = hsum2(ar[e]); p.y = hsum2(az[e]);
                p.z = hsum2(axn[e]); p.w = hsum2(ahn[e]);
                *(float4*)(s_pp + e * 128 + lane * 4) = p;
            }
            if (t + 1 < Tn) {
#pragma unroll
                for (int j = 0; j < 4; ++j)
                    s_x[(4 * hw + j) * Dn + lane] = xr[j];
                int tn = (t + 2 < Tn) ? (t + 2) : (Tn - 1);
#pragma unroll
                for (int j = 0; j < 4; ++j) {
                    int e = 4 * hw + j;
                    xr[j] = x[((eb + e) * Tn + tn) * Dn + lane];
                }
            }
        }
        asm volatile("bar.sync %0, %1;" :: "r"(barid), "r"(128) : "memory");  // #3

        // phase-1 consumer: kh==1 reduces + epilogue -> h2
        if (kh == 1) {
#pragma unroll
            for (int e = 0; e < EPW; ++e) {
                float4 p = *(const float4*)(s_pp + e * 128 + lane * 4);
                float r = sigmoid_f(hsum2(ar[e]) + p.x + Br1);
                float z = sigmoid_f(hsum2(az[e]) + p.y + Bz1);
                float n = tanh_f(fmaf(r, hsum2(ahn[e]) + p.w + Bhn1,
                                         hsum2(axn[e]) + p.z + Bxn1));
                float hp = s_h2[e * Hn + row];
                s_h2[e * Hn + row] = fmaf(z, hp - n, n);
            }
        }
        // h2 visibility for next t's gemm1 rides next iteration's bar #1/#2.
    }

    asm volatile("bar.sync %0, %1;" :: "r"(barid), "r"(128) : "memory");

    // ---- FC head: kh==1, hw==0 warp of each group ----
    if (kh == 1 && hw == 0) {
        const float fw0 = fc_w[lane];
        const float fw1 = fc_w[lane + 32];
        const float fb  = fc_b[0];
#pragma unroll
        for (int e = 0; e < EPW; ++e) {
            float v = fw0 * s_h2[e * Hn + lane] + fw1 * s_h2[e * Hn + lane + 32];
#pragma unroll
            for (int off = 16; off > 0; off >>= 1)
                v += __shfl_xor_sync(0xffffffffu, v, off);
            if (lane == 0) out[eb + e] = v + fb;
        }
    }
}

extern "C" void kernel_launch(void* const* d_in, const int* in_sizes, int n_in,
                              void* d_out, int out_size)
{
    const float* x     = (const float*)d_in[0];
    const float* W_ih0 = (const float*)d_in[1];
    const float* W_hh0 = (const float*)d_in[2];
    const float* b_ih0 = (const float*)d_in[3];
    const float* b_hh0 = (const float*)d_in[4];
    const float* W_ih1 = (const float*)d_in[5];
    const float* W_hh1 = (const float*)d_in[6];
    const float* b_ih1 = (const float*)d_in[7];
    const float* b_hh1 = (const float*)d_in[8];
    const float* fc_w  = (const float*)d_in[9];
    const float* fc_b  = (const float*)d_in[10];
    float* out = (float*)d_out;

    int batch = in_sizes[0] / (Tn * Dn);   // 4096
    int grid = batch / EPB;                // 128 blocks

    size_t smem = (size_t)SMEM_FLOATS * sizeof(float);  // 225280 B
    cudaFuncSetAttribute(gru_fused_kernel,
                         cudaFuncAttributeMaxDynamicSharedMemorySize, (int)smem);

    gru_fused_kernel<<<grid, TPB, smem>>>(x, W_ih0, W_hh0, b_ih0, b_hh0,
                                          W_ih1, W_hh1, b_ih1, b_hh1,
                                          fc_w, fc_b, out);
}

// round 9
// speedup vs baseline: 1.1243x; 1.1243x over previous
#include <cuda_runtime.h>

typedef unsigned long long u64;

#define Bn 4096
#define Tn 128
#define Dn 32
#define Hn 64
#define Gn 192   // 3*H

#define NWARP 8
#define TPB (NWARP * 32)  // 256 threads
#define NPAIR 4           // warp pairs per block
#define EPW 8             // batch elements per warp PAIR
#define EPB (NPAIR * EPW) // 32 elements per block

// Weight layout: s[(k>>2)*768 + g*4 + (k&3)] = W[g][k]   (quad-of-k packed per row)
#define OFF_W0X 0                        // [8][192][4]  = 6144
#define OFF_W0H (OFF_W0X + 8  * 768)    // 12288
#define OFF_W1I (OFF_W0H + 16 * 768)
#define OFF_W1H (OFF_W1I + 16 * 768)
#define OFF_H1  (OFF_W1H + 16 * 768)    // 43008: [4 pair][2 buf][8 e][64]
#define OFF_H2  (OFF_H1 + NPAIR * 2 * EPW * Hn)   // +4096 = 47104
#define OFF_X   (OFF_H2 + NPAIR * 2 * EPW * Hn)   // +4096 = 51200: [8 warp][8 e][32]
#define SMEM_FLOATS (OFF_X + NWARP * EPW * Dn)    // +2048 = 53248 floats = 212992 B

__device__ __forceinline__ void ffma2(u64& d, u64 a, u64 b) {
    asm("fma.rn.f32x2 %0, %1, %2, %0;" : "+l"(d) : "l"(a), "l"(b));
}
__device__ __forceinline__ float hsum2(u64 v) {
    float lo, hi;
    asm("mov.b64 {%0, %1}, %2;" : "=f"(lo), "=f"(hi) : "l"(v));
    return lo + hi;
}
__device__ __forceinline__ float sigmoid_f(float x) {
    return __fdividef(1.0f, 1.0f + __expf(-x));
}
__device__ __forceinline__ float tanh_f(float x) {
    float e = __expf(-2.0f * x);
    return __fdividef(1.0f - e, 1.0f + e);
}

struct u64x2 { u64 a, b; };
__device__ __forceinline__ u64x2 lds128(const float* p) {
    u64x2 r;
    ulonglong2 v = *(const ulonglong2*)p;
    r.a = v.x; r.b = v.y;
    return r;
}

__global__ void __launch_bounds__(TPB, 1)
gru_fused_kernel(const float* __restrict__ x,
                 const float* __restrict__ W_ih0, const float* __restrict__ W_hh0,
                 const float* __restrict__ b_ih0, const float* __restrict__ b_hh0,
                 const float* __restrict__ W_ih1, const float* __restrict__ W_hh1,
                 const float* __restrict__ b_ih1, const float* __restrict__ b_hh1,
                 const float* __restrict__ fc_w, const float* __restrict__ fc_b,
                 float* __restrict__ out)
{
    extern __shared__ float sm[];
    const int tid = threadIdx.x;

    // ---- stage weights ----
    for (int idx = tid; idx < Gn * Dn; idx += TPB) {
        int g = idx / Dn, k = idx - g * Dn;
        sm[OFF_W0X + (k >> 2) * 768 + g * 4 + (k & 3)] = W_ih0[idx];
    }
    for (int idx = tid; idx < Gn * Hn; idx += TPB) {
        int g = idx / Hn, k = idx - g * Hn;
        int d = (k >> 2) * 768 + g * 4 + (k & 3);
        sm[OFF_W0H + d] = W_hh0[idx];
        sm[OFF_W1I + d] = W_ih1[idx];
        sm[OFF_W1H + d] = W_hh1[idx];
    }
    __syncthreads();

    const int warp = tid >> 5;
    const int lane = tid & 31;
    // KEY CHANGE vs R6: pair = adjacent warps -> the two warps of a pair sit on
    // DIFFERENT SMSPs, and each SMSP hosts warps from two INDEPENDENT pairs.
    const int wg = warp >> 1;         // pair id (element group): warps {2wg, 2wg+1}
    const int hw = warp & 1;          // row half: 0 or 1
    const int barid = 1 + wg;
    const int eb = blockIdx.x * EPB + wg * EPW;

    const int row = lane + 32 * hw;   // this warp's row within each gate

    // h buffers: [pair][buf][e][64]
    float* h1b = sm + OFF_H1 + wg * (2 * EPW * Hn);
    float* h2b = sm + OFF_H2 + wg * (2 * EPW * Hn);
    float* s_x = sm + OFF_X  + warp * (EPW * Dn);   // per-warp private copy

    // zero the read buffer (buf 0) of h1/h2
#pragma unroll
    for (int e = 0; e < EPW; ++e) {
        h1b[e * Hn + row] = 0.0f;
        h2b[e * Hn + row] = 0.0f;
    }
    __syncthreads();

    // biases for this warp's rows
    const float Br0  = b_ih0[row]       + b_hh0[row];
    const float Bz0  = b_ih0[row + 64]  + b_hh0[row + 64];
    const float Bxn0 = b_ih0[row + 128];
    const float Bhn0 = b_hh0[row + 128];
    const float Br1  = b_ih1[row]       + b_hh1[row];
    const float Bz1  = b_ih1[row + 64]  + b_hh1[row + 64];
    const float Bxn1 = b_ih1[row + 128];
    const float Bhn1 = b_hh1[row + 128];

    // weight float4-base offsets within a quad block (float units)
    const int oR = row * 4;
    const int oZ = (row + 64) * 4;
    const int oN = (row + 128) * 4;

    u64 ar[EPW], az[EPW], axn[EPW], ahn[EPW];

    // prefetch t=0 x
    float xr[EPW];
#pragma unroll
    for (int e = 0; e < EPW; ++e)
        xr[e] = x[(eb + e) * (Tn * Dn) + lane];

    int rd = 0;   // read-buffer parity

    for (int t = 0; t < Tn; ++t) {
        const float* h1r = h1b + rd * (EPW * Hn);
        float*       h1w = h1b + (1 - rd) * (EPW * Hn);
        const float* h2r = h2b + rd * (EPW * Hn);
        float*       h2w = h2b + (1 - rd) * (EPW * Hn);

        // stage x (warp-private), prefetch next t
#pragma unroll
        for (int e = 0; e < EPW; ++e)
            s_x[e * Dn + lane] = xr[e];
        __syncwarp();
        if (t + 1 < Tn) {
#pragma unroll
            for (int e = 0; e < EPW; ++e)
                xr[e] = x[((eb + e) * Tn + t + 1) * Dn + lane];
        }

        // ================= layer 0 =================
#pragma unroll
        for (int e = 0; e < EPW; ++e) { ar[e] = 0; az[e] = 0; axn[e] = 0; ahn[e] = 0; }

#pragma unroll 2
        for (int q = 0; q < Dn / 4; ++q) {
            const float* wq = sm + OFF_W0X + q * 768;
            u64x2 wr = lds128(wq + oR);
            u64x2 wz = lds128(wq + oZ);
            u64x2 wn = lds128(wq + oN);
#pragma unroll
            for (int e = 0; e < EPW; ++e) {
                u64x2 xv = lds128(s_x + e * Dn + q * 4);   // broadcast
                ffma2(ar[e],  wr.a, xv.a); ffma2(ar[e],  wr.b, xv.b);
                ffma2(az[e],  wz.a, xv.a); ffma2(az[e],  wz.b, xv.b);
                ffma2(axn[e], wn.a, xv.a); ffma2(axn[e], wn.b, xv.b);
            }
        }
#pragma unroll 2
        for (int q = 0; q < Hn / 4; ++q) {
            const float* wq = sm + OFF_W0H + q * 768;
            u64x2 wr = lds128(wq + oR);
            u64x2 wz = lds128(wq + oZ);
            u64x2 wn = lds128(wq + oN);
#pragma unroll
            for (int e = 0; e < EPW; ++e) {
                u64x2 hv = lds128(h1r + e * Hn + q * 4);   // broadcast
                ffma2(ar[e],  wr.a, hv.a); ffma2(ar[e],  wr.b, hv.b);
                ffma2(az[e],  wz.a, hv.a); ffma2(az[e],  wz.b, hv.b);
                ffma2(ahn[e], wn.a, hv.a); ffma2(ahn[e], wn.b, hv.b);
            }
        }

        // gate epilogue -> h1_new (own row only), write to alternate buffer
#pragma unroll
        for (int e = 0; e < EPW; ++e) {
            float r = sigmoid_f(hsum2(ar[e]) + Br0);
            float z = sigmoid_f(hsum2(az[e]) + Bz0);
            float n = tanh_f(fmaf(r, hsum2(ahn[e]) + Bhn0, hsum2(axn[e]) + Bxn0));
            float hp = h1r[e * Hn + row];
            h1w[e * Hn + row] = fmaf(z, hp - n, n);
        }

        // the ONE cross-warp barrier per timestep: h1_new visible to pair peer
        asm volatile("bar.sync %0, %1;" :: "r"(barid), "r"(64) : "memory");

        // ================= layer 1 =================
#pragma unroll
        for (int e = 0; e < EPW; ++e) { ar[e] = 0; az[e] = 0; axn[e] = 0; ahn[e] = 0; }

#pragma unroll 1
        for (int q = 0; q < Hn / 4; ++q) {
            const float* wqi = sm + OFF_W1I + q * 768;
            const float* wqh = sm + OFF_W1H + q * 768;
            u64x2 ir = lds128(wqi + oR);
            u64x2 iz = lds128(wqi + oZ);
            u64x2 in = lds128(wqi + oN);
            u64x2 hr = lds128(wqh + oR);
            u64x2 hz = lds128(wqh + oZ);
            u64x2 hn = lds128(wqh + oN);
#pragma unroll
            for (int e = 0; e < EPW; ++e) {
                u64x2 av = lds128(h1w + e * Hn + q * 4);   // new h1 (layer-1 input)
                u64x2 bv = lds128(h2r + e * Hn + q * 4);   // prev h2
                ffma2(ar[e],  ir.a, av.a); ffma2(ar[e],  ir.b, av.b);
                ffma2(ar[e],  hr.a, bv.a); ffma2(ar[e],  hr.b, bv.b);
                ffma2(az[e],  iz.a, av.a); ffma2(az[e],  iz.b, av.b);
                ffma2(az[e],  hz.a, bv.a); ffma2(az[e],  hz.b, bv.b);
                ffma2(axn[e], in.a, av.a); ffma2(axn[e], in.b, av.b);
                ffma2(ahn[e], hn.a, bv.a); ffma2(ahn[e], hn.b, bv.b);
            }
        }

#pragma unroll
        for (int e = 0; e < EPW; ++e) {
            float r = sigmoid_f(hsum2(ar[e]) + Br1);
            float z = sigmoid_f(hsum2(az[e]) + Bz1);
            float n = tanh_f(fmaf(r, hsum2(ahn[e]) + Bhn1, hsum2(axn[e]) + Bxn1));
            float hp = h2r[e * Hn + row];
            h2w[e * Hn + row] = fmaf(z, hp - n, n);
        }

        rd ^= 1;
    }

    asm volatile("bar.sync %0, %1;" :: "r"(barid), "r"(64) : "memory");

    if (hw == 0) {
        const float* h2f = h2b + rd * (EPW * Hn);
        const float fw0 = fc_w[lane];
        const float fw1 = fc_w[lane + 32];
        const float fb  = fc_b[0];
#pragma unroll
        for (int e = 0; e < EPW; ++e) {
            float v = fw0 * h2f[e * Hn + lane] + fw1 * h2f[e * Hn + lane + 32];
#pragma unroll
            for (int off = 16; off > 0; off >>= 1)
                v += __shfl_xor_sync(0xffffffffu, v, off);
            if (lane == 0) out[eb + e] = v + fb;
        }
    }
}

extern "C" void kernel_launch(void* const* d_in, const int* in_sizes, int n_in,
                              void* d_out, int out_size)
{
    const float* x     = (const float*)d_in[0];
    const float* W_ih0 = (const float*)d_in[1];
    const float* W_hh0 = (const float*)d_in[2];
    const float* b_ih0 = (const float*)d_in[3];
    const float* b_hh0 = (const float*)d_in[4];
    const float* W_ih1 = (const float*)d_in[5];
    const float* W_hh1 = (const float*)d_in[6];
    const float* b_ih1 = (const float*)d_in[7];
    const float* b_hh1 = (const float*)d_in[8];
    const float* fc_w  = (const float*)d_in[9];
    const float* fc_b  = (const float*)d_in[10];
    float* out = (float*)d_out;

    int batch = in_sizes[0] / (Tn * Dn);   // 4096
    int grid = batch / EPB;                // 128 blocks

    size_t smem = (size_t)SMEM_FLOATS * sizeof(float);  // 212992 B
    cudaFuncSetAttribute(gru_fused_kernel,
                         cudaFuncAttributeMaxDynamicSharedMemorySize, (int)smem);

    gru_fused_kernel<<<grid, TPB, smem>>>(x, W_ih0, W_hh0, b_ih0, b_hh0,
                                          W_ih1, W_hh1, b_ih1, b_hh1,
                                          fc_w, fc_b, out);
}

// round 10
// speedup vs baseline: 1.1643x; 1.0356x over previous
#include <cuda_runtime.h>

typedef unsigned long long u64;

#define Bn 4096
#define Tn 128
#define Dn 32
#define Hn 64
#define Gn 192   // 3*H

#define NWARP 8
#define TPB (NWARP * 32)  // 256 threads
#define NPAIR 4           // warp pairs per block
#define EPW 8             // batch elements per warp PAIR
#define EPB (NPAIR * EPW) // 32 elements per block

// Weight layout: s[(k>>2)*768 + g*4 + (k&3)] = W[g][k]
#define OFF_W0X 0
#define OFF_W0H (OFF_W0X + 8  * 768)
#define OFF_W1I (OFF_W0H + 16 * 768)
#define OFF_W1H (OFF_W1I + 16 * 768)
#define OFF_H1  (OFF_W1H + 16 * 768)              // [4 pair][2 buf][8 e][64]
#define OFF_H2  (OFF_H1 + NPAIR * 2 * EPW * Hn)
#define OFF_X   (OFF_H2 + NPAIR * 2 * EPW * Hn)   // [8 warp][8 e][32]
#define SMEM_FLOATS (OFF_X + NWARP * EPW * Dn)    // 53248 floats = 212992 B

__device__ __forceinline__ void ffma2(u64& d, u64 a, u64 b) {
    asm("fma.rn.f32x2 %0, %1, %2, %0;" : "+l"(d) : "l"(a), "l"(b));
}
__device__ __forceinline__ float hsum2(u64 v) {
    float lo, hi;
    asm("mov.b64 {%0, %1}, %2;" : "=f"(lo), "=f"(hi) : "l"(v));
    return lo + hi;
}
__device__ __forceinline__ float sigmoid_f(float x) {
    return __fdividef(1.0f, 1.0f + __expf(-x));
}
__device__ __forceinline__ float tanh_f(float x) {
    float e = __expf(-2.0f * x);
    return __fdividef(1.0f - e, 1.0f + e);
}

struct u64x2 { u64 a, b; };
__device__ __forceinline__ u64x2 lds128(const float* p) {
    u64x2 r;
    ulonglong2 v = *(const ulonglong2*)p;
    r.a = v.x; r.b = v.y;
    return r;
}

__global__ void __launch_bounds__(TPB, 1)
gru_fused_kernel(const float* __restrict__ x,
                 const float* __restrict__ W_ih0, const float* __restrict__ W_hh0,
                 const float* __restrict__ b_ih0, const float* __restrict__ b_hh0,
                 const float* __restrict__ W_ih1, const float* __restrict__ W_hh1,
                 const float* __restrict__ b_ih1, const float* __restrict__ b_hh1,
                 const float* __restrict__ fc_w, const float* __restrict__ fc_b,
                 float* __restrict__ out)
{
    extern __shared__ float sm[];
    const int tid = threadIdx.x;

    // ---- stage weights ----
    for (int idx = tid; idx < Gn * Dn; idx += TPB) {
        int g = idx / Dn, k = idx - g * Dn;
        sm[OFF_W0X + (k >> 2) * 768 + g * 4 + (k & 3)] = W_ih0[idx];
    }
    for (int idx = tid; idx < Gn * Hn; idx += TPB) {
        int g = idx / Hn, k = idx - g * Hn;
        int d = (k >> 2) * 768 + g * 4 + (k & 3);
        sm[OFF_W0H + d] = W_hh0[idx];
        sm[OFF_W1I + d] = W_ih1[idx];
        sm[OFF_W1H + d] = W_hh1[idx];
    }
    __syncthreads();

    const int warp = tid >> 5;
    const int lane = tid & 31;
    const int wg = warp >> 1;         // pair id: warps {2wg, 2wg+1} on different SMSPs
    const int hw = warp & 1;          // row half
    const int barid = 1 + wg;
    const int eb = blockIdx.x * EPB + wg * EPW;

    const int row = lane + 32 * hw;

    float* h1b = sm + OFF_H1 + wg * (2 * EPW * Hn);
    float* h2b = sm + OFF_H2 + wg * (2 * EPW * Hn);
    float* s_x = sm + OFF_X  + warp * (EPW * Dn);

#pragma unroll
    for (int e = 0; e < EPW; ++e) {
        h1b[e * Hn + row] = 0.0f;
        h2b[e * Hn + row] = 0.0f;
    }
    __syncthreads();

    const float Br0  = b_ih0[row]       + b_hh0[row];
    const float Bz0  = b_ih0[row + 64]  + b_hh0[row + 64];
    const float Bxn0 = b_ih0[row + 128];
    const float Bhn0 = b_hh0[row + 128];
    const float Br1  = b_ih1[row]       + b_hh1[row];
    const float Bz1  = b_ih1[row + 64]  + b_hh1[row + 64];
    const float Bxn1 = b_ih1[row + 128];
    const float Bhn1 = b_hh1[row + 128];

    const int oR = row * 4;
    const int oZ = (row + 64) * 4;
    const int oN = (row + 128) * 4;

    u64 ar[EPW], az[EPW], axn[EPW], ahn[EPW];

    // own-row h kept in registers (removes LDS at epilogue head)
    float h1own[EPW], h2own[EPW];
#pragma unroll
    for (int e = 0; e < EPW; ++e) { h1own[e] = 0.0f; h2own[e] = 0.0f; }

    // prefetch t=0 x
    float xr[EPW];
#pragma unroll
    for (int e = 0; e < EPW; ++e)
        xr[e] = x[(eb + e) * (Tn * Dn) + lane];

    int rd = 0;

    for (int t = 0; t < Tn; ++t) {
        const float* h1r = h1b + rd * (EPW * Hn);
        float*       h1w = h1b + (1 - rd) * (EPW * Hn);
        const float* h2r = h2b + rd * (EPW * Hn);
        float*       h2w = h2b + (1 - rd) * (EPW * Hn);

        // stage x, prefetch next t
#pragma unroll
        for (int e = 0; e < EPW; ++e)
            s_x[e * Dn + lane] = xr[e];
        __syncwarp();
        if (t + 1 < Tn) {
#pragma unroll
            for (int e = 0; e < EPW; ++e)
                xr[e] = x[((eb + e) * Tn + t + 1) * Dn + lane];
        }

        // ================= layer 0 =================
#pragma unroll
        for (int e = 0; e < EPW; ++e) { ar[e] = 0; az[e] = 0; axn[e] = 0; ahn[e] = 0; }

        // x-side: all quad loads batched before FMA block
#pragma unroll 4
        for (int q = 0; q < Dn / 4; ++q) {
            const float* wq = sm + OFF_W0X + q * 768;
            u64x2 wr = lds128(wq + oR);
            u64x2 wz = lds128(wq + oZ);
            u64x2 wn = lds128(wq + oN);
            u64x2 xv[EPW];
#pragma unroll
            for (int e = 0; e < EPW; ++e)
                xv[e] = lds128(s_x + e * Dn + q * 4);
#pragma unroll
            for (int e = 0; e < EPW; ++e) {
                ffma2(ar[e],  wr.a, xv[e].a); ffma2(ar[e],  wr.b, xv[e].b);
                ffma2(az[e],  wz.a, xv[e].a); ffma2(az[e],  wz.b, xv[e].b);
                ffma2(axn[e], wn.a, xv[e].a); ffma2(axn[e], wn.b, xv[e].b);
            }
        }
        // h-side
#pragma unroll 4
        for (int q = 0; q < Hn / 4; ++q) {
            const float* wq = sm + OFF_W0H + q * 768;
            u64x2 wr = lds128(wq + oR);
            u64x2 wz = lds128(wq + oZ);
            u64x2 wn = lds128(wq + oN);
            u64x2 hv[EPW];
#pragma unroll
            for (int e = 0; e < EPW; ++e)
                hv[e] = lds128(h1r + e * Hn + q * 4);
#pragma unroll
            for (int e = 0; e < EPW; ++e) {
                ffma2(ar[e],  wr.a, hv[e].a); ffma2(ar[e],  wr.b, hv[e].b);
                ffma2(az[e],  wz.a, hv[e].a); ffma2(az[e],  wz.b, hv[e].b);
                ffma2(ahn[e], wn.a, hv[e].a); ffma2(ahn[e], wn.b, hv[e].b);
            }
        }

        // epilogue -> h1_new (own row), registers + alternate smem buffer
#pragma unroll
        for (int e = 0; e < EPW; ++e) {
            float r = sigmoid_f(hsum2(ar[e]) + Br0);
            float z = sigmoid_f(hsum2(az[e]) + Bz0);
            float n = tanh_f(fmaf(r, hsum2(ahn[e]) + Bhn0, hsum2(axn[e]) + Bxn0));
            float hn_ = fmaf(z, h1own[e] - n, n);
            h1own[e] = hn_;
            h1w[e * Hn + row] = hn_;
        }

        asm volatile("bar.sync %0, %1;" :: "r"(barid), "r"(64) : "memory");

        // ================= layer 1 =================
#pragma unroll
        for (int e = 0; e < EPW; ++e) { ar[e] = 0; az[e] = 0; axn[e] = 0; ahn[e] = 0; }

#pragma unroll 2
        for (int q = 0; q < Hn / 4; ++q) {
            const float* wqi = sm + OFF_W1I + q * 768;
            const float* wqh = sm + OFF_W1H + q * 768;
            u64x2 ir = lds128(wqi + oR);
            u64x2 iz = lds128(wqi + oZ);
            u64x2 in = lds128(wqi + oN);
            u64x2 hr = lds128(wqh + oR);
            u64x2 hz = lds128(wqh + oZ);
            u64x2 hn = lds128(wqh + oN);
            u64x2 av[EPW], bv[EPW];
#pragma unroll
            for (int e = 0; e < EPW; ++e) {
                av[e] = lds128(h1w + e * Hn + q * 4);
                bv[e] = lds128(h2r + e * Hn + q * 4);
            }
#pragma unroll
            for (int e = 0; e < EPW; ++e) {
                ffma2(ar[e],  ir.a, av[e].a); ffma2(ar[e],  ir.b, av[e].b);
                ffma2(az[e],  iz.a, av[e].a); ffma2(az[e],  iz.b, av[e].b);
                ffma2(axn[e], in.a, av[e].a); ffma2(axn[e], in.b, av[e].b);
                ffma2(ar[e],  hr.a, bv[e].a); ffma2(ar[e],  hr.b, bv[e].b);
                ffma2(az[e],  hz.a, bv[e].a); ffma2(az[e],  hz.b, bv[e].b);
                ffma2(ahn[e], hn.a, bv[e].a); ffma2(ahn[e], hn.b, bv[e].b);
            }
        }

#pragma unroll
        for (int e = 0; e < EPW; ++e) {
            float r = sigmoid_f(hsum2(ar[e]) + Br1);
            float z = sigmoid_f(hsum2(az[e]) + Bz1);
            float n = tanh_f(fmaf(r, hsum2(ahn[e]) + Bhn1, hsum2(axn[e]) + Bxn1));
            float hn_ = fmaf(z, h2own[e] - n, n);
            h2own[e] = hn_;
            h2w[e * Hn + row] = hn_;
        }

        rd ^= 1;
    }

    asm volatile("bar.sync %0, %1;" :: "r"(barid), "r"(64) : "memory");

    // ---- FC head ----
    if (hw == 0) {
        const float* h2f = h2b + rd * (EPW * Hn);
        const float fw0 = fc_w[lane];
        const float fw1 = fc_w[lane + 32];
        const float fb  = fc_b[0];
#pragma unroll
        for (int e = 0; e < EPW; ++e) {
            float v = fw0 * h2own[e] + fw1 * h2f[e * Hn + lane + 32];
#pragma unroll
            for (int off = 16; off > 0; off >>= 1)
                v += __shfl_xor_sync(0xffffffffu, v, off);
            if (lane == 0) out[eb + e] = v + fb;
        }
    }
}

extern "C" void kernel_launch(void* const* d_in, const int* in_sizes, int n_in,
                              void* d_out, int out_size)
{
    const float* x     = (const float*)d_in[0];
    const float* W_ih0 = (const float*)d_in[1];
    const float* W_hh0 = (const float*)d_in[2];
    const float* b_ih0 = (const float*)d_in[3];
    const float* b_hh0 = (const float*)d_in[4];
    const float* W_ih1 = (const float*)d_in[5];
    const float* W_hh1 = (const float*)d_in[6];
    const float* b_ih1 = (const float*)d_in[7];
    const float* b_hh1 = (const float*)d_in[8];
    const float* fc_w  = (const float*)d_in[9];
    const float* fc_b  = (const float*)d_in[10];
    float* out = (float*)d_out;

    int batch = in_sizes[0] / (Tn * Dn);   // 4096
    int grid = batch / EPB;                // 128 blocks

    size_t smem = (size_t)SMEM_FLOATS * sizeof(float);  // 212992 B
    cudaFuncSetAttribute(gru_fused_kernel,
                         cudaFuncAttributeMaxDynamicSharedMemorySize, (int)smem);

    gru_fused_kernel<<<grid, TPB, smem>>>(x, W_ih0, W_hh0, b_ih0, b_hh0,
                                          W_ih1, W_hh1, b_ih1, b_hh1,
                                          fc_w, fc_b, out);
}